// round 9
// baseline (speedup 1.0000x reference)
#include <cuda_runtime.h>
#include <stdint.h>

#define N_OBJ 16384
#define N_DIM 4096
#define GDIM  8                 // dims per block
#define HB    4096              // fine histogram bins (C > HB -> fallback)
#define INV_SQRT2 0.70710678118654752440f

__device__ int g_flag[N_DIM];   // written every launch (no pre-zero needed)

// thr(j) = 0.05f * float32((j+1)/16384)
__device__ __forceinline__ float thr(int j) {
    return __fmul_rn(0.05f, (float)(j + 1) * 6.103515625e-05f);
}

// bin = min{j : p <= thr(j)}, or -1 if p > 0.05. Thresholds are uniform in p,
// so an arithmetic estimate + <=1-step fp fixup is exact.
__device__ __forceinline__ int compute_bin(float m, float v) {
    // p = 0.5*erfc(x), x = (mu/v)/sqrt2. Clamp x>=1: p(1)=0.0786 > 0.05, so
    // clamped values land in the invalid region regardless.
    float x = __fdividef(m, v) * INV_SQRT2;
    float xc = fmaxf(x, 1.0f);
    float h = xc * xc;                       // exp(-x^2), Dekker-corrected
    float l = fmaf(xc, xc, -h);
    float e = __expf(-h);
    e = fmaf(-l, e, e);
    float den = fmaf(0.3275911f, xc, 1.0f);  // A&S 7.1.26, |err| <= 1.5e-7
    float t = __fdividef(1.0f, den);
    float poly = fmaf(t, 1.061405429f, -1.453152027f);
    poly = fmaf(t, poly, 1.421413741f);
    poly = fmaf(t, poly, -0.284496736f);
    poly = fmaf(t, poly, 0.254829592f);
    float p = 0.5f * t * poly * e;
    if (!(p <= 0.05f)) return -1;            // thr(16383) == 0.05f exactly
    int j = (int)ceilf(p * 327680.0f) - 1;
    j = min(max(j, 0), N_OBJ - 1);
    while (j > 0 && p <= thr(j - 1)) --j;
    while (j < N_OBJ - 1 && p > thr(j)) ++j;
    return j;
}

// ---------------- fused kernel: stream input -> 8 smem hists -> scan ------
// Block 1024: half = tid&1 picks dim-quad (float4), og = tid>>1 picks object.
// Each iteration processes 512 objects x 8 dims; 32 iterations total.
__global__ void __launch_bounds__(1024, 1) fused_kernel(
        const float* __restrict__ q_mu, const float* __restrict__ q_var,
        float* __restrict__ out) {
    extern __shared__ uint32_t h32[];        // GDIM * HB/2 u32 = 64 KB (u16 pairs)
    __shared__ uint32_t s_cnt[GDIM];
    __shared__ uint32_t warp_part[32];
    __shared__ uint32_t red_cnt[32];
    __shared__ int      red_min[32];
    __shared__ uint32_t s_out[GDIM];

    const int tid = threadIdx.x, lane = tid & 31, wid = tid >> 5;
    const int db = blockIdx.x * GDIM;

    for (int k = tid; k < GDIM * (HB / 2); k += 1024) h32[k] = 0;
    if (tid < GDIM) s_cnt[tid] = 0;
    __syncthreads();

    const int half = tid & 1;                // dim-quad within the 8 dims
    const int og   = tid >> 1;               // 0..511
    const float4* mu4  = (const float4*)q_mu;
    const float4* var4 = (const float4*)q_var;
    const size_t cbase = (size_t)(db >> 2) + half;
    uint32_t* hq = h32 + half * 4 * (HB / 2);

    uint32_t cA = 0, cB = 0;                 // valid counts, u16 fields (<=32 each)

    size_t a0 = (size_t)og * (N_DIM / 4) + cbase;
    float4 m = mu4[a0];
    float4 v = var4[a0];
    for (int it = 0; it < 32; ++it) {
        float4 mn, vn;
        if (it < 31) {                       // prefetch next iteration
            size_t a = (size_t)((it + 1) * 512 + og) * (N_DIM / 4) + cbase;
            mn = mu4[a]; vn = var4[a];
        }
        int j0 = compute_bin(m.x, v.x);
        if (j0 >= 0) { cA += 1u;        if (j0 < HB) atomicAdd(&hq[0 * (HB/2) + (j0 >> 1)], 1u << ((j0 & 1) << 4)); }
        int j1 = compute_bin(m.y, v.y);
        if (j1 >= 0) { cA += 1u << 16;  if (j1 < HB) atomicAdd(&hq[1 * (HB/2) + (j1 >> 1)], 1u << ((j1 & 1) << 4)); }
        int j2 = compute_bin(m.z, v.z);
        if (j2 >= 0) { cB += 1u;        if (j2 < HB) atomicAdd(&hq[2 * (HB/2) + (j2 >> 1)], 1u << ((j2 & 1) << 4)); }
        int j3 = compute_bin(m.w, v.w);
        if (j3 >= 0) { cB += 1u << 16;  if (j3 < HB) atomicAdd(&hq[3 * (HB/2) + (j3 >> 1)], 1u << ((j3 & 1) << 4)); }
        m = mn; v = vn;
    }

    // reduce packed counts across same-parity lanes (shfl_xor keeps parity);
    // fields stay <= 16*32 = 512, no u16 overflow.
    #pragma unroll
    for (int o = 2; o <= 16; o <<= 1) {
        cA += __shfl_xor_sync(0xffffffffu, cA, o);
        cB += __shfl_xor_sync(0xffffffffu, cB, o);
    }
    if (lane < 2) {
        atomicAdd(&s_cnt[lane * 4 + 0], cA & 0xFFFFu);
        atomicAdd(&s_cnt[lane * 4 + 1], cA >> 16);
        atomicAdd(&s_cnt[lane * 4 + 2], cB & 0xFFFFu);
        atomicAdd(&s_cnt[lane * 4 + 3], cB >> 16);
    }
    __syncthreads();

    // epilogue: per dim, scan 4096 bins (4 bins/thread), reject[j]=cum(j)>=j+1
    for (int dq = 0; dq < GDIM; dq++) {
        const uint32_t* hw = h32 + dq * (HB / 2);
        uint32_t w0 = hw[tid * 2], w1 = hw[tid * 2 + 1];
        uint32_t b0 = w0 & 0xFFFFu, b1 = w0 >> 16;
        uint32_t b2 = w1 & 0xFFFFu, b3 = w1 >> 16;
        uint32_t s4 = b0 + b1 + b2 + b3;

        uint32_t x = s4;
        #pragma unroll
        for (int o = 1; o < 32; o <<= 1) {
            uint32_t y = __shfl_up_sync(0xffffffffu, x, o);
            if (lane >= o) x += y;
        }
        if (lane == 31) warp_part[wid] = x;
        __syncthreads();
        if (wid == 0) {
            uint32_t ww = warp_part[lane];
            #pragma unroll
            for (int o = 1; o < 32; o <<= 1) {
                uint32_t y = __shfl_up_sync(0xffffffffu, ww, o);
                if (lane >= o) ww += y;
            }
            warp_part[lane] = ww;
        }
        __syncthreads();

        uint32_t cum = x - s4 + (wid > 0 ? warp_part[wid - 1] : 0u);
        int jb = tid * 4;
        uint32_t cnt = 0;
        int fj = 0x7fffffff;
        cum += b0; if (cum >= (uint32_t)(jb + 1)) { cnt++; fj = jb; }
        cum += b1; if (cum >= (uint32_t)(jb + 2)) { cnt++; fj = min(fj, jb + 1); }
        cum += b2; if (cum >= (uint32_t)(jb + 3)) { cnt++; fj = min(fj, jb + 2); }
        cum += b3; if (cum >= (uint32_t)(jb + 4)) { cnt++; fj = min(fj, jb + 3); }

        #pragma unroll
        for (int o = 16; o > 0; o >>= 1) {
            cnt += __shfl_down_sync(0xffffffffu, cnt, o);
            fj = min(fj, __shfl_down_sync(0xffffffffu, fj, o));
        }
        if (lane == 0) { red_cnt[wid] = cnt; red_min[wid] = fj; }
        __syncthreads();
        if (wid == 0) {
            uint32_t cc = red_cnt[lane];
            int mm = red_min[lane];
            #pragma unroll
            for (int o = 16; o > 0; o >>= 1) {
                cc += __shfl_down_sync(0xffffffffu, cc, o);
                mm = min(mm, __shfl_down_sync(0xffffffffu, mm, o));
            }
            if (lane == 0) s_out[dq] = cc + ((mm == 0x7fffffff) ? 0u : (uint32_t)mm);
        }
        __syncthreads();
    }

    if (tid < GDIM) {
        g_flag[db + tid] = (s_cnt[tid] > (uint32_t)HB) ? 1 : 0;
        out[db + tid] = (float)s_out[tid];   // fallback overwrites if flagged
    }
}

// ---------------- fallback: exact full-range recompute for flagged dims ---
// Statistically never runs (C > 4096 is a >25-sigma event) but guarantees
// correctness. Uncoalesced column reads are irrelevant at this frequency.
__global__ void __launch_bounds__(1024) fallback_kernel(
        const float* __restrict__ q_mu, const float* __restrict__ q_var,
        float* __restrict__ out) {
    __shared__ uint32_t h[N_OBJ / 2];        // u16-packed 16384 bins = 32 KB
    __shared__ uint32_t warp_part[32];
    __shared__ uint32_t s_carry;
    __shared__ uint32_t red_cnt[32];
    __shared__ int      red_min[32];

    const int d = blockIdx.x;
    if (!g_flag[d]) return;

    const int tid = threadIdx.x, lane = tid & 31, wid = tid >> 5;
    for (int k = tid; k < N_OBJ / 2; k += 1024) h[k] = 0;
    if (tid == 0) s_carry = 0;
    __syncthreads();

    for (int k = tid; k < N_OBJ; k += 1024) {
        float m = q_mu[(size_t)k * N_DIM + d];
        float v = q_var[(size_t)k * N_DIM + d];
        int j = compute_bin(m, v);
        if (j >= 0) atomicAdd(&h[j >> 1], 1u << ((j & 1) << 4));
    }
    __syncthreads();

    uint32_t count = 0;
    int firstj = 0x7fffffff;
    for (int c = 0; c < 16; ++c) {
        int j = c * 1024 + tid;
        uint32_t x = (h[j >> 1] >> ((j & 1) << 4)) & 0xFFFFu;
        uint32_t binv = x;
        #pragma unroll
        for (int o = 1; o < 32; o <<= 1) {
            uint32_t y = __shfl_up_sync(0xffffffffu, x, o);
            if (lane >= o) x += y;
        }
        if (lane == 31) warp_part[wid] = x;
        __syncthreads();
        if (wid == 0) {
            uint32_t ww = warp_part[lane];
            #pragma unroll
            for (int o = 1; o < 32; o <<= 1) {
                uint32_t y = __shfl_up_sync(0xffffffffu, ww, o);
                if (lane >= o) ww += y;
            }
            warp_part[lane] = ww;
        }
        __syncthreads();
        uint32_t incl = x + (wid > 0 ? warp_part[wid - 1] : 0u) + s_carry;
        (void)binv;
        if (incl >= (uint32_t)(j + 1)) { count++; firstj = min(firstj, j); }
        __syncthreads();
        if (tid == 0) s_carry += warp_part[31];
        __syncthreads();
    }

    #pragma unroll
    for (int o = 16; o > 0; o >>= 1) {
        count += __shfl_down_sync(0xffffffffu, count, o);
        firstj = min(firstj, __shfl_down_sync(0xffffffffu, firstj, o));
    }
    if (lane == 0) { red_cnt[wid] = count; red_min[wid] = firstj; }
    __syncthreads();
    if (wid == 0) {
        uint32_t cc = red_cnt[lane];
        int mm = red_min[lane];
        #pragma unroll
        for (int o = 16; o > 0; o >>= 1) {
            cc += __shfl_down_sync(0xffffffffu, cc, o);
            mm = min(mm, __shfl_down_sync(0xffffffffu, mm, o));
        }
        if (lane == 0)
            out[d] = (float)(cc + ((mm == 0x7fffffff) ? 0u : (uint32_t)mm));
    }
}

extern "C" void kernel_launch(void* const* d_in, const int* in_sizes, int n_in,
                              void* d_out, int out_size) {
    const float* q_mu  = (const float*)d_in[0];
    const float* q_var = (const float*)d_in[1];
    float* out = (float*)d_out;

    const int smem = GDIM * (HB / 2) * (int)sizeof(uint32_t);   // 64 KB
    cudaFuncSetAttribute((const void*)fused_kernel,
                         cudaFuncAttributeMaxDynamicSharedMemorySize, smem);

    fused_kernel<<<N_DIM / GDIM, 1024, smem>>>(q_mu, q_var, out);
    fallback_kernel<<<N_DIM, 1024>>>(q_mu, q_var, out);
}

// round 10
// speedup vs baseline: 1.8882x; 1.8882x over previous
#include <cuda_runtime.h>
#include <stdint.h>

#define N_OBJ 16384
#define N_DIM 4096
#define HB    4096              // stored fine bins; C > HB -> exact slow path
#define HW    (HB / 2)          // u32 words per dim (u16-packed pairs)
#define INV_SQRT2 0.70710678118654752440f

__device__ uint32_t g_hist[(size_t)N_DIM * HW];   // 32 MB, L2-resident
__device__ uint32_t g_cnt[N_DIM];

// thr(j) = 0.05f * float32((j+1)/16384)
__device__ __forceinline__ float thr(int j) {
    return __fmul_rn(0.05f, (float)(j + 1) * 6.103515625e-05f);
}

// bin = min{j : p <= thr(j)}, or -1 if p > 0.05. Thresholds uniform in p:
// arithmetic estimate + <=1-step fp fixup is exact.
__device__ __forceinline__ int compute_bin(float m, float v) {
    // p = 0.5*erfc(x), x = (mu/v)/sqrt2. Clamp x>=1: p(1)=0.0786 > 0.05.
    float x = __fdividef(m, v) * INV_SQRT2;
    float xc = fmaxf(x, 1.0f);
    float h = xc * xc;                       // exp(-x^2), Dekker-corrected
    float l = fmaf(xc, xc, -h);
    float e = __expf(-h);
    e = fmaf(-l, e, e);
    float den = fmaf(0.3275911f, xc, 1.0f);  // A&S 7.1.26, |err| <= 1.5e-7
    float t = __fdividef(1.0f, den);
    float poly = fmaf(t, 1.061405429f, -1.453152027f);
    poly = fmaf(t, poly, 1.421413741f);
    poly = fmaf(t, poly, -0.284496736f);
    poly = fmaf(t, poly, 0.254829592f);
    float p = 0.5f * t * poly * e;
    if (!(p <= 0.05f)) return -1;            // thr(16383) == 0.05f exactly
    int j = (int)ceilf(p * 327680.0f) - 1;
    j = min(max(j, 0), N_OBJ - 1);
    while (j > 0 && p <= thr(j - 1)) --j;
    while (j < N_OBJ - 1 && p > thr(j)) ++j;
    return j;
}

// ---------------- zero: hist + counts (every launch; graph-safe) ----------
__global__ void zero_kernel() {
    size_t i = (size_t)blockIdx.x * 1024 + threadIdx.x;     // 2048*1024 threads
    ((uint4*)g_hist)[i] = make_uint4(0u, 0u, 0u, 0u);       // 8.4M words exactly
    if (i < N_DIM) g_cnt[i] = 0;
}

// ---------------- phase 1: stream -> RED into global hist -----------------
// Block 256 = (32 tx=dim, 8 ty=obj), 8 objs/thread -> tile 32 dims x 64 objs.
// Fire-and-forget RED atomics only (no returned values -> no latency chains).
__global__ void __launch_bounds__(256) phase1_kernel(
        const float* __restrict__ q_mu, const float* __restrict__ q_var) {
    __shared__ uint32_t s_cnt[32];

    const int tid = threadIdx.x, tx = tid & 31, ty = tid >> 5;
    const int d = blockIdx.x * 32 + tx;
    const size_t base = (size_t)(blockIdx.y * 64 + ty) * N_DIM + d;

    if (tid < 32) s_cnt[tid] = 0;
    __syncthreads();

    float mm[8], vv[8];
    #pragma unroll
    for (int r = 0; r < 8; r++) {            // streaming loads: evict-first
        mm[r] = __ldcs(q_mu  + base + (size_t)(r * 8) * N_DIM);
        vv[r] = __ldcs(q_var + base + (size_t)(r * 8) * N_DIM);
    }

    uint32_t* hrow = g_hist + (size_t)d * HW;
    uint32_t cnt = 0;
    #pragma unroll
    for (int r = 0; r < 8; r++) {
        int j = compute_bin(mm[r], vv[r]);
        if (j >= 0) {
            cnt++;
            if (j < HB)
                atomicAdd(&hrow[j >> 1], 1u << ((j & 1) << 4));  // RED (packed u16)
        }
    }
    // per-block per-dim aggregation: lane==dim -> conflict-free ATOMS
    if (cnt) atomicAdd(&s_cnt[tx], cnt);
    __syncthreads();
    if (tid < 32 && s_cnt[tid])
        atomicAdd(&g_cnt[blockIdx.x * 32 + tid], s_cnt[tid]);    // RED
}

// ---------------- phase 2: per-dim scan of L2-resident hist ---------------
__global__ void __launch_bounds__(1024) phase2_kernel(
        const float* __restrict__ q_mu, const float* __restrict__ q_var,
        float* __restrict__ out) {
    __shared__ uint32_t warp_part[32];
    __shared__ uint32_t red_cnt[32];
    __shared__ int      red_min[32];
    __shared__ uint32_t s_slow[N_OBJ / 2];   // 32 KB, slow path only

    const int tid = threadIdx.x, lane = tid & 31, wid = tid >> 5;
    const int d = blockIdx.x;
    const uint32_t C = g_cnt[d];

    if (C == 0) { if (tid == 0) out[d] = 0.0f; return; }

    uint32_t b0, b1, b2, b3;
    uint32_t count = 0;
    int firstj = 0x7fffffff;

    if (C <= (uint32_t)HB) {
        // fast path: single 4096-bin scan, 4 bins/thread, coalesced u32 pairs
        const uint32_t* hw = g_hist + (size_t)d * HW + tid * 2;
        uint32_t w0 = hw[0], w1 = hw[1];
        b0 = w0 & 0xFFFFu; b1 = w0 >> 16; b2 = w1 & 0xFFFFu; b3 = w1 >> 16;
        uint32_t s4 = b0 + b1 + b2 + b3;

        uint32_t x = s4;
        #pragma unroll
        for (int o = 1; o < 32; o <<= 1) {
            uint32_t y = __shfl_up_sync(0xffffffffu, x, o);
            if (lane >= o) x += y;
        }
        if (lane == 31) warp_part[wid] = x;
        __syncthreads();
        if (wid == 0) {
            uint32_t ww = warp_part[lane];
            #pragma unroll
            for (int o = 1; o < 32; o <<= 1) {
                uint32_t y = __shfl_up_sync(0xffffffffu, ww, o);
                if (lane >= o) ww += y;
            }
            warp_part[lane] = ww;
        }
        __syncthreads();

        uint32_t cum = x - s4 + (wid > 0 ? warp_part[wid - 1] : 0u);
        int jb = tid * 4;
        cum += b0; if (cum >= (uint32_t)(jb + 1)) { count++; firstj = jb; }
        cum += b1; if (cum >= (uint32_t)(jb + 2)) { count++; firstj = min(firstj, jb + 1); }
        cum += b2; if (cum >= (uint32_t)(jb + 3)) { count++; firstj = min(firstj, jb + 2); }
        cum += b3; if (cum >= (uint32_t)(jb + 4)) { count++; firstj = min(firstj, jb + 3); }
    } else {
        // slow path (C > 4096: >25-sigma event, never in practice): exact
        // full-range recompute with a 16384-bin smem histogram.
        for (int k = tid; k < N_OBJ / 2; k += 1024) s_slow[k] = 0;
        __syncthreads();
        for (int k = tid; k < N_OBJ; k += 1024) {
            float m = q_mu[(size_t)k * N_DIM + d];
            float v = q_var[(size_t)k * N_DIM + d];
            int j = compute_bin(m, v);
            if (j >= 0) atomicAdd(&s_slow[j >> 1], 1u << ((j & 1) << 4));
        }
        __syncthreads();
        uint32_t carry = 0;
        for (int c = 0; c < 16; ++c) {
            int j = c * 1024 + tid;
            uint32_t bv = (s_slow[j >> 1] >> ((j & 1) << 4)) & 0xFFFFu;
            uint32_t x = bv;
            #pragma unroll
            for (int o = 1; o < 32; o <<= 1) {
                uint32_t y = __shfl_up_sync(0xffffffffu, x, o);
                if (lane >= o) x += y;
            }
            if (lane == 31) warp_part[wid] = x;
            __syncthreads();
            if (wid == 0) {
                uint32_t ww = warp_part[lane];
                #pragma unroll
                for (int o = 1; o < 32; o <<= 1) {
                    uint32_t y = __shfl_up_sync(0xffffffffu, ww, o);
                    if (lane >= o) ww += y;
                }
                warp_part[lane] = ww;
            }
            __syncthreads();
            uint32_t incl = x + (wid > 0 ? warp_part[wid - 1] : 0u) + carry;
            if (incl >= (uint32_t)(j + 1)) { count++; firstj = min(firstj, j); }
            __syncthreads();
            carry += warp_part[31];
            __syncthreads();
        }
    }

    // block reduce (sum count, min firstj)
    #pragma unroll
    for (int o = 16; o > 0; o >>= 1) {
        count += __shfl_down_sync(0xffffffffu, count, o);
        firstj = min(firstj, __shfl_down_sync(0xffffffffu, firstj, o));
    }
    if (lane == 0) { red_cnt[wid] = count; red_min[wid] = firstj; }
    __syncthreads();
    if (wid == 0) {
        uint32_t cc = red_cnt[lane];
        int mm = red_min[lane];
        #pragma unroll
        for (int o = 16; o > 0; o >>= 1) {
            cc += __shfl_down_sync(0xffffffffu, cc, o);
            mm = min(mm, __shfl_down_sync(0xffffffffu, mm, o));
        }
        if (lane == 0)
            out[d] = (float)(cc + ((mm == 0x7fffffff) ? 0u : (uint32_t)mm));
    }
}

extern "C" void kernel_launch(void* const* d_in, const int* in_sizes, int n_in,
                              void* d_out, int out_size) {
    const float* q_mu  = (const float*)d_in[0];
    const float* q_var = (const float*)d_in[1];
    float* out = (float*)d_out;

    zero_kernel<<<(N_DIM * HW / 4) / 1024, 1024>>>();        // 2048 blocks
    dim3 g1(N_DIM / 32, N_OBJ / 64);
    phase1_kernel<<<g1, 256>>>(q_mu, q_var);
    phase2_kernel<<<N_DIM, 1024>>>(q_mu, q_var, out);
}